// round 16
// baseline (speedup 1.0000x reference)
#include <cuda_runtime.h>
#include <math.h>
#include <math_constants.h>
#include <stdint.h>

// Problem constants
constexpr int cB = 4;
constexpr int cS = 2048;
constexpr int cH = 2048;
constexpr int cH2 = cH / 2;
constexpr int cM = cB * cS;               // 8192
constexpr size_t SH = (size_t)cS * cH;
constexpr size_t SSz = (size_t)cS * cS;
constexpr size_t MHz = (size_t)cM * cH;
constexpr size_t WN = (size_t)cH * cH;

// ---------------- scratch ---------------------------------------------------
__device__ float g_cos[SH / 2];   // only first half (mirrored)
__device__ float g_sin[SH / 2];
__device__ float g_qrot[MHz];
__device__ float g_krot[MHz];
__device__ float g_vin[MHz];
__device__ float g_wq[WN];
__device__ float g_wk[WN];
__device__ float g_wv[WN];
__device__ float g_wo[WN];
__device__ float g_q[MHz];
__device__ float g_k[MHz];
__device__ float g_vT[MHz];       // v projected AND transposed [H][M]
__device__ float g_s[(size_t)cB * SSz];
__device__ float g_ctx[MHz];

// ---------------- helpers ---------------------------------------------------
__device__ __forceinline__ float tf32r(float x) {
    uint32_t u;
    asm("cvt.rna.tf32.f32 %0, %1;" : "=r"(u) : "f"(x));
    return __uint_as_float(u);
}

#define CPA16(smem_u32, gptr) \
    asm volatile("cp.async.cg.shared.global [%0], [%1], 16;" :: "r"(smem_u32), "l"(gptr))

#define LDSM4(r0, r1, r2, r3, a) \
    asm volatile("ldmatrix.sync.aligned.m8n8.x4.shared.b16 {%0,%1,%2,%3}, [%4];" \
                 : "=r"(r0), "=r"(r1), "=r"(r2), "=r"(r3) : "r"(a))

// ---------------- RoPE tables (first half only; second half mirrors) --------
__global__ void rope_tables_kernel() {
    int idx = blockIdx.x * blockDim.x + threadIdx.x;
    if (idx >= cS * cH2) return;
    int s = idx / cH2;
    int j = idx % cH2;
    float f = (float)pow(10000.0, -2.0 * (double)j / (double)cH);
    float ang = (float)s * f;
    float sn, cs;
    sincosf(ang, &sn, &cs);
    g_cos[(size_t)s * cH2 + j] = cs;
    g_sin[(size_t)s * cH2 + j] = sn;
}

// RoPE on q,k + tf32-round v; each thread handles a (h, h+H/2) float4 PAIR.
__global__ void rope_apply_v_kernel(const float* __restrict__ q,
                                    const float* __restrict__ k,
                                    const float* __restrict__ v) {
    constexpr int J4 = cH2 / 4;               // 256 float4 per half-row
    size_t idx = (size_t)blockIdx.x * blockDim.x + threadIdx.x;
    if (idx >= (size_t)cM * J4) return;
    const int m = (int)(idx / J4);
    const int j4 = (int)(idx % J4);
    const int s = m & (cS - 1);
    const size_t tbl = (size_t)s * cH2 + j4 * 4;
    const size_t b1 = (size_t)m * cH + j4 * 4;
    const size_t b2 = b1 + cH2;

    float4 c  = *(const float4*)(g_cos + tbl);
    float4 sn = *(const float4*)(g_sin + tbl);

    float4 q1 = *(const float4*)(q + b1);
    float4 q2 = *(const float4*)(q + b2);
    float4 o1, o2;
    o1.x = tf32r(q1.x * c.x - q2.x * sn.x); o2.x = tf32r(q2.x * c.x + q1.x * sn.x);
    o1.y = tf32r(q1.y * c.y - q2.y * sn.y); o2.y = tf32r(q2.y * c.y + q1.y * sn.y);
    o1.z = tf32r(q1.z * c.z - q2.z * sn.z); o2.z = tf32r(q2.z * c.z + q1.z * sn.z);
    o1.w = tf32r(q1.w * c.w - q2.w * sn.w); o2.w = tf32r(q2.w * c.w + q1.w * sn.w);
    *(float4*)(g_qrot + b1) = o1;
    *(float4*)(g_qrot + b2) = o2;

    float4 k1 = *(const float4*)(k + b1);
    float4 k2 = *(const float4*)(k + b2);
    o1.x = tf32r(k1.x * c.x - k2.x * sn.x); o2.x = tf32r(k2.x * c.x + k1.x * sn.x);
    o1.y = tf32r(k1.y * c.y - k2.y * sn.y); o2.y = tf32r(k2.y * c.y + k1.y * sn.y);
    o1.z = tf32r(k1.z * c.z - k2.z * sn.z); o2.z = tf32r(k2.z * c.z + k1.z * sn.z);
    o1.w = tf32r(k1.w * c.w - k2.w * sn.w); o2.w = tf32r(k2.w * c.w + k1.w * sn.w);
    *(float4*)(g_krot + b1) = o1;
    *(float4*)(g_krot + b2) = o2;

    float4 v1 = *(const float4*)(v + b1);
    float4 v2 = *(const float4*)(v + b2);
    v1.x = tf32r(v1.x); v1.y = tf32r(v1.y); v1.z = tf32r(v1.z); v1.w = tf32r(v1.w);
    v2.x = tf32r(v2.x); v2.y = tf32r(v2.y); v2.z = tf32r(v2.z); v2.w = tf32r(v2.w);
    *(float4*)(g_vin + b1) = v1;
    *(float4*)(g_vin + b2) = v2;
}

// round all 4 weight matrices: grid (WN/4/256, 4)
__global__ void round_weights_kernel(const float* __restrict__ w0,
                                     const float* __restrict__ w1,
                                     const float* __restrict__ w2,
                                     const float* __restrict__ w3) {
    const float* src = (blockIdx.y == 0) ? w0 : (blockIdx.y == 1) ? w1
                     : (blockIdx.y == 2) ? w2 : w3;
    float* dst = (blockIdx.y == 0) ? g_wq : (blockIdx.y == 1) ? g_wk
               : (blockIdx.y == 2) ? g_wv : g_wo;
    size_t i = (size_t)blockIdx.x * blockDim.x + threadIdx.x;
    float4 v = ((const float4*)src)[i];
    v.x = tf32r(v.x); v.y = tf32r(v.y); v.z = tf32r(v.z); v.w = tf32r(v.w);
    ((float4*)dst)[i] = v;
}

// ---------------- mma.sync TF32 GEMM core (8 warps, 64x32 warp tiles) -------
// C[m,n] = sum_k A[m,k] * B[n,k] (+bias[n]); B [N][K] K-major.
// Block 128x128x32, 256 threads, 3-stage cp.async, ldmatrix frags, 2 CTA/SM.
// MODE: 0 = plain store, 1 = tf32-rounded store, 2 = TRANSPOSED store.
constexpr int BK = 32;
constexpr int TILE_B = 128 * BK * 4;
constexpr int STG = 2 * TILE_B;
constexpr int NSTG = 3;
constexpr int GEMM_SMEM = NSTG * STG + 1024;  // 99328 (2 CTA/SM)

template<int MODE>
__device__ __forceinline__ void gemm_core(
    const float* __restrict__ Ab, const float* __restrict__ Bb,
    const float* __restrict__ bias, float* __restrict__ Cb,
    int Kd, int lda, int ldb, int ldc, int bm, int bn) {
    extern __shared__ float smf[];
    uint32_t sbase = (uint32_t)__cvta_generic_to_shared(smf);
    sbase = (sbase + 1023u) & ~1023u;

    const int tid = threadIdx.x;
    const int lane = tid & 31;
    const int w = tid >> 5;
    const int wm = (w >> 2) * 64;
    const int wn = (w & 3) * 32;
    const int g = lane >> 2;
    const int tig = lane & 3;
    const int nk = Kd / BK;

    const int r0 = tid >> 3;
    const int ch = tid & 7;
    const uint32_t swoff = (uint32_t)((ch * 16) ^ ((r0 & 7) << 4));
    const uint32_t ldOffA = (uint32_t)(r0 * 128) + swoff;
    const float* gA0 = Ab + (size_t)(bm + r0) * lda + ch * 4;
    const float* gB0 = Bb + (size_t)(bn + r0) * ldb + ch * 4;
    const size_t gAs = 32 * (size_t)lda;
    const size_t gBs = 32 * (size_t)ldb;

    // A fragment addresses (ldmatrix x4: rows g/g+8 x k lo/hi)
    const int aRowOff = ((lane >> 3) & 1) * 8 + (lane & 7);
    const uint32_t aCS = (uint32_t)((lane >> 4) * 16);
    uint32_t aRB[4], aRX[4];
#pragma unroll
    for (int i = 0; i < 4; i++) {
        int row = wm + i * 16 + aRowOff;
        aRB[i] = (uint32_t)(row * 128);
        aRX[i] = (uint32_t)((row & 7) << 4);
    }
    // B fragment addresses (ldmatrix x4 covers a j-pair)
    const uint32_t bCS = (uint32_t)(((lane >> 3) & 1) * 16);
    uint32_t bRB[2], bRX[2];
#pragma unroll
    for (int p = 0; p < 2; p++) {
        int row = wn + p * 16 + ((lane >> 4) * 8) + (lane & 7);
        bRB[p] = (uint32_t)(row * 128);
        bRX[p] = (uint32_t)((row & 7) << 4);
    }

    float acc[4][4][4];
#pragma unroll
    for (int i = 0; i < 4; i++)
#pragma unroll
        for (int j = 0; j < 4; j++)
#pragma unroll
            for (int r = 0; r < 4; r++) acc[i][j][r] = 0.f;

#pragma unroll
    for (int t = 0; t < 2; t++) {
        const uint32_t ds = sbase + t * STG;
        const float* ga = gA0 + (size_t)t * BK;
        const float* gb = gB0 + (size_t)t * BK;
#pragma unroll
        for (int u = 0; u < 4; u++) {
            CPA16(ds + ldOffA + u * 4096, ga + u * gAs);
            CPA16(ds + TILE_B + ldOffA + u * 4096, gb + u * gBs);
        }
        asm volatile("cp.async.commit_group;");
    }

    int s = 0, sp = 2;
    for (int t = 0; t < nk; t++) {
        asm volatile("cp.async.wait_group 1;");
        __syncthreads();

        if (t + 2 < nk) {
            const uint32_t ds = sbase + sp * STG;
            const float* ga = gA0 + (size_t)(t + 2) * BK;
            const float* gb = gB0 + (size_t)(t + 2) * BK;
#pragma unroll
            for (int u = 0; u < 4; u++) {
                CPA16(ds + ldOffA + u * 4096, ga + u * gAs);
                CPA16(ds + TILE_B + ldOffA + u * 4096, gb + u * gBs);
            }
        }
        asm volatile("cp.async.commit_group;");

        const uint32_t aB = sbase + s * STG;
        const uint32_t bB = aB + TILE_B;
#pragma unroll
        for (int ks = 0; ks < 4; ks++) {
            const uint32_t kcol = (uint32_t)(ks * 32);
            uint32_t af[4][4], bf[4][2];
#pragma unroll
            for (int i = 0; i < 4; i++)
                LDSM4(af[i][0], af[i][1], af[i][2], af[i][3],
                      aB + aRB[i] + ((kcol + aCS) ^ aRX[i]));
#pragma unroll
            for (int p = 0; p < 2; p++)
                LDSM4(bf[2 * p][0], bf[2 * p][1], bf[2 * p + 1][0], bf[2 * p + 1][1],
                      bB + bRB[p] + ((kcol + bCS) ^ bRX[p]));
#pragma unroll
            for (int i = 0; i < 4; i++)
#pragma unroll
                for (int j = 0; j < 4; j++) {
                    asm volatile(
                        "mma.sync.aligned.m16n8k8.row.col.f32.tf32.tf32.f32 "
                        "{%0,%1,%2,%3}, {%4,%5,%6,%7}, {%8,%9}, {%0,%1,%2,%3};"
                        : "+f"(acc[i][j][0]), "+f"(acc[i][j][1]),
                          "+f"(acc[i][j][2]), "+f"(acc[i][j][3])
                        : "r"(af[i][0]), "r"(af[i][1]), "r"(af[i][2]), "r"(af[i][3]),
                          "r"(bf[j][0]), "r"(bf[j][1]));
                }
        }
        s = (s == NSTG - 1) ? 0 : s + 1;
        sp = (sp == NSTG - 1) ? 0 : sp + 1;
    }

    if (MODE == 2) {
        // -------- transposed epilogue: SMEM [n][m] staging (pad 132) --------
        __syncthreads();
#pragma unroll
        for (int i = 0; i < 4; i++) {
            const int rr0 = wm + i * 16 + g;
            const int rr1 = rr0 + 8;
#pragma unroll
            for (int j = 0; j < 4; j++) {
                const int cc = wn + j * 8 + 2 * tig;
                const float b0 = bias[bn + cc];
                const float b1 = bias[bn + cc + 1];
                smf[(cc + 0) * 132 + rr0] = tf32r(acc[i][j][0] + b0);
                smf[(cc + 1) * 132 + rr0] = tf32r(acc[i][j][1] + b1);
                smf[(cc + 0) * 132 + rr1] = tf32r(acc[i][j][2] + b0);
                smf[(cc + 1) * 132 + rr1] = tf32r(acc[i][j][3] + b1);
            }
        }
        __syncthreads();
        // coalesced write: vT[(bn+nl)][bm + m], row = 128 floats
        const int nl = tid >> 1;
        const int m0 = (tid & 1) * 64;
        float* orow = Cb + (size_t)(bn + nl) * cM + bm + m0;
        const float* srow = smf + nl * 132 + m0;
#pragma unroll
        for (int u = 0; u < 16; u++) {
            float4 vv;
            vv.x = srow[u * 4 + 0];
            vv.y = srow[u * 4 + 1];
            vv.z = srow[u * 4 + 2];
            vv.w = srow[u * 4 + 3];
            *(float4*)(orow + u * 4) = vv;
        }
    } else {
#pragma unroll
        for (int i = 0; i < 4; i++) {
            const int rr0 = bm + wm + i * 16 + g;
            const int rr1 = rr0 + 8;
#pragma unroll
            for (int j = 0; j < 4; j++) {
                const int cc = bn + wn + j * 8 + 2 * tig;
                float b0 = 0.f, b1 = 0.f;
                if (bias) { b0 = bias[cc]; b1 = bias[cc + 1]; }
                float2 v0, v1;
                v0.x = acc[i][j][0] + b0; v0.y = acc[i][j][1] + b1;
                v1.x = acc[i][j][2] + b0; v1.y = acc[i][j][3] + b1;
                if (MODE == 1) {
                    v0.x = tf32r(v0.x); v0.y = tf32r(v0.y);
                    v1.x = tf32r(v1.x); v1.y = tf32r(v1.y);
                }
                *(float2*)(Cb + (size_t)rr0 * ldc + cc) = v0;
                *(float2*)(Cb + (size_t)rr1 * ldc + cc) = v1;
            }
        }
    }
}

// Q,K projections only: grid (16, 64, 2)
__global__ __launch_bounds__(256, 2)
void gemm2_proj(const float* __restrict__ bq, const float* __restrict__ bk) {
    const int bm = blockIdx.y * 128, bn = blockIdx.x * 128;
    if (blockIdx.z == 0)
        gemm_core<1>(g_qrot, g_wq, bq, g_q, cH, cH, cH, cH, bm, bn);
    else
        gemm_core<1>(g_krot, g_wk, bk, g_k, cH, cH, cH, cH, bm, bn);
}

// V-projection + scores FUSED (independent work, merged to kill wave tails):
// grid (16, 64, 2): z=0 -> v-proj tile (bm=y*128), writes g_vT transposed;
//                   z=1 -> scores tile: batch = y>>4, row tile = y&15.
__global__ __launch_bounds__(256, 2)
void gemm_vs(const float* __restrict__ bv) {
    const int bn = blockIdx.x * 128;
    if (blockIdx.z == 0) {
        gemm_core<2>(g_vin, g_wv, bv, g_vT, cH, cH, cH, cM,
                     blockIdx.y * 128, bn);
    } else {
        const int b = blockIdx.y >> 4;
        const int bm = (blockIdx.y & 15) * 128;
        gemm_core<0>(g_q + b * SH, g_k + b * SH, nullptr, g_s + b * SSz,
                     cH, cH, cH, cS, bm, bn);
    }
}

__global__ __launch_bounds__(256, 2)
void gemm_bat0(const float* __restrict__ A, const float* __restrict__ Bm,
               const float* __restrict__ bias, float* __restrict__ C,
               int Kd, int lda, int ldb, int ldc,
               size_t strA, size_t strB, size_t strC) {
    gemm_core<0>(A + blockIdx.z * strA, Bm + blockIdx.z * strB, bias,
                 C + blockIdx.z * strC, Kd, lda, ldb, ldc,
                 blockIdx.y * 128, blockIdx.x * 128);
}

__global__ __launch_bounds__(256, 2)
void gemm_bat1(const float* __restrict__ A, const float* __restrict__ Bm,
               const float* __restrict__ bias, float* __restrict__ C,
               int Kd, int lda, int ldb, int ldc,
               size_t strA, size_t strB, size_t strC) {
    gemm_core<1>(A + blockIdx.z * strA, Bm + blockIdx.z * strB, bias,
                 C + blockIdx.z * strC, Kd, lda, ldb, ldc,
                 blockIdx.y * 128, blockIdx.x * 128);
}

// ---------------- softmax (float4 vectorized; same reduction order) ---------
__global__ void softmax_kernel(float* __restrict__ Sc, float scale) {
    const size_t row = blockIdx.x;
    float4* p = (float4*)(Sc + row * (size_t)cS);   // 512 float4 per row
    const int tid = threadIdx.x;                    // 256 threads
    __shared__ float smax[8];
    __shared__ float ssum[8];

    float4 a = p[tid];
    float4 b = p[tid + 256];
    float v[8];
    v[0] = a.x * scale; v[1] = a.y * scale; v[2] = a.z * scale; v[3] = a.w * scale;
    v[4] = b.x * scale; v[5] = b.y * scale; v[6] = b.z * scale; v[7] = b.w * scale;

    float m = -CUDART_INF_F;
#pragma unroll
    for (int i = 0; i < 8; i++) m = fmaxf(m, v[i]);
#pragma unroll
    for (int o = 16; o > 0; o >>= 1)
        m = fmaxf(m, __shfl_xor_sync(0xffffffffu, m, o));
    if ((tid & 31) == 0) smax[tid >> 5] = m;
    __syncthreads();
    m = smax[0];
#pragma unroll
    for (int w = 1; w < 8; w++) m = fmaxf(m, smax[w]);

    float s = 0.f;
#pragma unroll
    for (int i = 0; i < 8; i++) {
        v[i] = expf(v[i] - m);
        s += v[i];
    }
#pragma unroll
    for (int o = 16; o > 0; o >>= 1)
        s += __shfl_xor_sync(0xffffffffu, s, o);
    if ((tid & 31) == 0) ssum[tid >> 5] = s;
    __syncthreads();
    s = 0.f;
#pragma unroll
    for (int w = 0; w < 8; w++) s += ssum[w];
    const float inv = 1.0f / s;

    a.x = tf32r(v[0] * inv); a.y = tf32r(v[1] * inv);
    a.z = tf32r(v[2] * inv); a.w = tf32r(v[3] * inv);
    b.x = tf32r(v[4] * inv); b.y = tf32r(v[5] * inv);
    b.z = tf32r(v[6] * inv); b.w = tf32r(v[7] * inv);
    p[tid] = a;
    p[tid + 256] = b;
}

// ---------------- launch ----------------------------------------------------
extern "C" void kernel_launch(void* const* d_in, const int* in_sizes, int n_in,
                              void* d_out, int out_size) {
    const float* query = (const float*)d_in[0];
    const float* key_  = (const float*)d_in[1];
    const float* value = (const float*)d_in[2];
    const float* Wq = (const float*)d_in[3];
    const float* bq = (const float*)d_in[4];
    const float* Wk = (const float*)d_in[5];
    const float* bk = (const float*)d_in[6];
    const float* Wv = (const float*)d_in[7];
    const float* bv = (const float*)d_in[8];
    const float* Wo = (const float*)d_in[9];
    const float* bo = (const float*)d_in[10];
    float* out = (float*)d_out;

    float *p_vT, *p_s, *p_ctx, *p_wo;
    cudaGetSymbolAddress((void**)&p_vT, g_vT);
    cudaGetSymbolAddress((void**)&p_s, g_s);
    cudaGetSymbolAddress((void**)&p_ctx, g_ctx);
    cudaGetSymbolAddress((void**)&p_wo, g_wo);

    cudaFuncSetAttribute(gemm2_proj,
                         cudaFuncAttributeMaxDynamicSharedMemorySize, GEMM_SMEM);
    cudaFuncSetAttribute(gemm_vs,
                         cudaFuncAttributeMaxDynamicSharedMemorySize, GEMM_SMEM);
    cudaFuncSetAttribute(gemm_bat0,
                         cudaFuncAttributeMaxDynamicSharedMemorySize, GEMM_SMEM);
    cudaFuncSetAttribute(gemm_bat1,
                         cudaFuncAttributeMaxDynamicSharedMemorySize, GEMM_SMEM);

    // 1) RoPE tables; RoPE(q,k) + round(v)
    rope_tables_kernel<<<(cS * cH2 + 255) / 256, 256>>>();
    rope_apply_v_kernel<<<(int)((size_t)cM * (cH2 / 4) / 256), 256>>>(query, key_, value);

    // 2) round all weights (one launch)
    round_weights_kernel<<<dim3((unsigned)(WN / 4 / 256), 4), 256>>>(Wq, Wk, Wv, Wo);

    // 3) Q,K projections (2048 CTAs — clean wave count)
    gemm2_proj<<<dim3(16, 64, 2), 256, GEMM_SMEM>>>(bq, bk);

    // 4) V-projection + scores fused (2048 CTAs — tails merged)
    gemm_vs<<<dim3(16, 64, 2), 256, GEMM_SMEM>>>(bv);

    // 5) softmax
    const float scale = 1.0f / sqrtf((float)cH);
    softmax_kernel<<<cB * cS, 256>>>(p_s, scale);

    // 6) context = probs @ vT^T (batched)
    gemm_bat1<<<dim3(16, 16, cB), 256, GEMM_SMEM>>>(p_s, p_vT, nullptr, p_ctx,
                                                    cS, cS, cM, cH, SSz, (size_t)cS, SH);

    // 7) out = ctx @ Wo^T + bo
    gemm_bat0<<<dim3(16, 64, 1), 256, GEMM_SMEM>>>(p_ctx, p_wo, bo, out,
                                                   cH, cH, cH, cH, 0, 0, 0);
}

// round 17
// speedup vs baseline: 1.0070x; 1.0070x over previous
#include <cuda_runtime.h>
#include <math.h>
#include <math_constants.h>
#include <stdint.h>

// Problem constants
constexpr int cB = 4;
constexpr int cS = 2048;
constexpr int cH = 2048;
constexpr int cH2 = cH / 2;
constexpr int cM = cB * cS;               // 8192
constexpr size_t SH = (size_t)cS * cH;
constexpr size_t SSz = (size_t)cS * cS;
constexpr size_t MHz = (size_t)cM * cH;
constexpr size_t WN = (size_t)cH * cH;

// ---------------- scratch ---------------------------------------------------
__device__ float g_cos[SH / 2];   // only first half (mirrored)
__device__ float g_sin[SH / 2];
__device__ float g_qrot[MHz];
__device__ float g_krot[MHz];
__device__ float g_vin[MHz];
__device__ float g_wq[WN];
__device__ float g_wk[WN];
__device__ float g_wv[WN];
__device__ float g_wo[WN];
__device__ float g_q[MHz];
__device__ float g_k[MHz];
__device__ float g_vT[MHz];       // v projected AND transposed [H][M]
__device__ float g_s[(size_t)cB * SSz];
__device__ float g_ctx[MHz];

// ---------------- helpers ---------------------------------------------------
__device__ __forceinline__ float tf32r(float x) {
    uint32_t u;
    asm("cvt.rna.tf32.f32 %0, %1;" : "=r"(u) : "f"(x));
    return __uint_as_float(u);
}

#define CPA16(smem_u32, gptr) \
    asm volatile("cp.async.cg.shared.global [%0], [%1], 16;" :: "r"(smem_u32), "l"(gptr))

#define LDSM4(r0, r1, r2, r3, a) \
    asm volatile("ldmatrix.sync.aligned.m8n8.x4.shared.b16 {%0,%1,%2,%3}, [%4];" \
                 : "=r"(r0), "=r"(r1), "=r"(r2), "=r"(r3) : "r"(a))

// ---------------- RoPE tables (first half only; second half mirrors) --------
__global__ void rope_tables_kernel() {
    int idx = blockIdx.x * blockDim.x + threadIdx.x;
    if (idx >= cS * cH2) return;
    int s = idx / cH2;
    int j = idx % cH2;
    float f = (float)pow(10000.0, -2.0 * (double)j / (double)cH);
    float ang = (float)s * f;
    float sn, cs;
    sincosf(ang, &sn, &cs);
    g_cos[(size_t)s * cH2 + j] = cs;
    g_sin[(size_t)s * cH2 + j] = sn;
}

// RoPE on q,k + tf32-round v; each thread handles a (h, h+H/2) float4 PAIR.
__global__ void rope_apply_v_kernel(const float* __restrict__ q,
                                    const float* __restrict__ k,
                                    const float* __restrict__ v) {
    constexpr int J4 = cH2 / 4;               // 256 float4 per half-row
    size_t idx = (size_t)blockIdx.x * blockDim.x + threadIdx.x;
    if (idx >= (size_t)cM * J4) return;
    const int m = (int)(idx / J4);
    const int j4 = (int)(idx % J4);
    const int s = m & (cS - 1);
    const size_t tbl = (size_t)s * cH2 + j4 * 4;
    const size_t b1 = (size_t)m * cH + j4 * 4;
    const size_t b2 = b1 + cH2;

    float4 c  = *(const float4*)(g_cos + tbl);
    float4 sn = *(const float4*)(g_sin + tbl);

    float4 q1 = *(const float4*)(q + b1);
    float4 q2 = *(const float4*)(q + b2);
    float4 o1, o2;
    o1.x = tf32r(q1.x * c.x - q2.x * sn.x); o2.x = tf32r(q2.x * c.x + q1.x * sn.x);
    o1.y = tf32r(q1.y * c.y - q2.y * sn.y); o2.y = tf32r(q2.y * c.y + q1.y * sn.y);
    o1.z = tf32r(q1.z * c.z - q2.z * sn.z); o2.z = tf32r(q2.z * c.z + q1.z * sn.z);
    o1.w = tf32r(q1.w * c.w - q2.w * sn.w); o2.w = tf32r(q2.w * c.w + q1.w * sn.w);
    *(float4*)(g_qrot + b1) = o1;
    *(float4*)(g_qrot + b2) = o2;

    float4 k1 = *(const float4*)(k + b1);
    float4 k2 = *(const float4*)(k + b2);
    o1.x = tf32r(k1.x * c.x - k2.x * sn.x); o2.x = tf32r(k2.x * c.x + k1.x * sn.x);
    o1.y = tf32r(k1.y * c.y - k2.y * sn.y); o2.y = tf32r(k2.y * c.y + k1.y * sn.y);
    o1.z = tf32r(k1.z * c.z - k2.z * sn.z); o2.z = tf32r(k2.z * c.z + k1.z * sn.z);
    o1.w = tf32r(k1.w * c.w - k2.w * sn.w); o2.w = tf32r(k2.w * c.w + k1.w * sn.w);
    *(float4*)(g_krot + b1) = o1;
    *(float4*)(g_krot + b2) = o2;

    float4 v1 = *(const float4*)(v + b1);
    float4 v2 = *(const float4*)(v + b2);
    v1.x = tf32r(v1.x); v1.y = tf32r(v1.y); v1.z = tf32r(v1.z); v1.w = tf32r(v1.w);
    v2.x = tf32r(v2.x); v2.y = tf32r(v2.y); v2.z = tf32r(v2.z); v2.w = tf32r(v2.w);
    *(float4*)(g_vin + b1) = v1;
    *(float4*)(g_vin + b2) = v2;
}

// round all 4 weight matrices: grid (WN/4/256, 4)
__global__ void round_weights_kernel(const float* __restrict__ w0,
                                     const float* __restrict__ w1,
                                     const float* __restrict__ w2,
                                     const float* __restrict__ w3) {
    const float* src = (blockIdx.y == 0) ? w0 : (blockIdx.y == 1) ? w1
                     : (blockIdx.y == 2) ? w2 : w3;
    float* dst = (blockIdx.y == 0) ? g_wq : (blockIdx.y == 1) ? g_wk
               : (blockIdx.y == 2) ? g_wv : g_wo;
    size_t i = (size_t)blockIdx.x * blockDim.x + threadIdx.x;
    float4 v = ((const float4*)src)[i];
    v.x = tf32r(v.x); v.y = tf32r(v.y); v.z = tf32r(v.z); v.w = tf32r(v.w);
    ((float4*)dst)[i] = v;
}

// ---------------- shared GEMM constants --------------------------------------
constexpr int BK = 32;
constexpr int TILE_B = 128 * BK * 4;
constexpr int STG = 2 * TILE_B;
constexpr int NSTG = 3;
constexpr int GEMM_SMEM = NSTG * STG + 1024;  // 99328 (2 CTA/SM)

// ---------------- gemm_core: 256 threads, 8 warps of 64x32 ------------------
// MODE: 0 = plain store, 1 = tf32-rounded store.
template<int MODE>
__device__ __forceinline__ void gemm_core(
    const float* __restrict__ Ab, const float* __restrict__ Bb,
    const float* __restrict__ bias, float* __restrict__ Cb,
    int Kd, int lda, int ldb, int ldc, int bm, int bn) {
    extern __shared__ float smf[];
    uint32_t sbase = (uint32_t)__cvta_generic_to_shared(smf);
    sbase = (sbase + 1023u) & ~1023u;

    const int tid = threadIdx.x;
    const int lane = tid & 31;
    const int w = tid >> 5;
    const int wm = (w >> 2) * 64;
    const int wn = (w & 3) * 32;
    const int g = lane >> 2;
    const int tig = lane & 3;
    const int nk = Kd / BK;

    const int r0 = tid >> 3;
    const int ch = tid & 7;
    const uint32_t swoff = (uint32_t)((ch * 16) ^ ((r0 & 7) << 4));
    const uint32_t ldOffA = (uint32_t)(r0 * 128) + swoff;
    const float* gA0 = Ab + (size_t)(bm + r0) * lda + ch * 4;
    const float* gB0 = Bb + (size_t)(bn + r0) * ldb + ch * 4;
    const size_t gAs = 32 * (size_t)lda;
    const size_t gBs = 32 * (size_t)ldb;

    const int aRowOff = ((lane >> 3) & 1) * 8 + (lane & 7);
    const uint32_t aCS = (uint32_t)((lane >> 4) * 16);
    uint32_t aRB[4], aRX[4];
#pragma unroll
    for (int i = 0; i < 4; i++) {
        int row = wm + i * 16 + aRowOff;
        aRB[i] = (uint32_t)(row * 128);
        aRX[i] = (uint32_t)((row & 7) << 4);
    }
    const uint32_t bCS = (uint32_t)(((lane >> 3) & 1) * 16);
    uint32_t bRB[2], bRX[2];
#pragma unroll
    for (int p = 0; p < 2; p++) {
        int row = wn + p * 16 + ((lane >> 4) * 8) + (lane & 7);
        bRB[p] = (uint32_t)(row * 128);
        bRX[p] = (uint32_t)((row & 7) << 4);
    }

    float acc[4][4][4];
#pragma unroll
    for (int i = 0; i < 4; i++)
#pragma unroll
        for (int j = 0; j < 4; j++)
#pragma unroll
            for (int r = 0; r < 4; r++) acc[i][j][r] = 0.f;

#pragma unroll
    for (int t = 0; t < 2; t++) {
        const uint32_t ds = sbase + t * STG;
        const float* ga = gA0 + (size_t)t * BK;
        const float* gb = gB0 + (size_t)t * BK;
#pragma unroll
        for (int u = 0; u < 4; u++) {
            CPA16(ds + ldOffA + u * 4096, ga + u * gAs);
            CPA16(ds + TILE_B + ldOffA + u * 4096, gb + u * gBs);
        }
        asm volatile("cp.async.commit_group;");
    }

    int s = 0, sp = 2;
    for (int t = 0; t < nk; t++) {
        asm volatile("cp.async.wait_group 1;");
        __syncthreads();

        if (t + 2 < nk) {
            const uint32_t ds = sbase + sp * STG;
            const float* ga = gA0 + (size_t)(t + 2) * BK;
            const float* gb = gB0 + (size_t)(t + 2) * BK;
#pragma unroll
            for (int u = 0; u < 4; u++) {
                CPA16(ds + ldOffA + u * 4096, ga + u * gAs);
                CPA16(ds + TILE_B + ldOffA + u * 4096, gb + u * gBs);
            }
        }
        asm volatile("cp.async.commit_group;");

        const uint32_t aB = sbase + s * STG;
        const uint32_t bB = aB + TILE_B;
#pragma unroll
        for (int ks = 0; ks < 4; ks++) {
            const uint32_t kcol = (uint32_t)(ks * 32);
            uint32_t af[4][4], bf[4][2];
#pragma unroll
            for (int i = 0; i < 4; i++)
                LDSM4(af[i][0], af[i][1], af[i][2], af[i][3],
                      aB + aRB[i] + ((kcol + aCS) ^ aRX[i]));
#pragma unroll
            for (int p = 0; p < 2; p++)
                LDSM4(bf[2 * p][0], bf[2 * p][1], bf[2 * p + 1][0], bf[2 * p + 1][1],
                      bB + bRB[p] + ((kcol + bCS) ^ bRX[p]));
#pragma unroll
            for (int i = 0; i < 4; i++)
#pragma unroll
                for (int j = 0; j < 4; j++) {
                    asm volatile(
                        "mma.sync.aligned.m16n8k8.row.col.f32.tf32.tf32.f32 "
                        "{%0,%1,%2,%3}, {%4,%5,%6,%7}, {%8,%9}, {%0,%1,%2,%3};"
                        : "+f"(acc[i][j][0]), "+f"(acc[i][j][1]),
                          "+f"(acc[i][j][2]), "+f"(acc[i][j][3])
                        : "r"(af[i][0]), "r"(af[i][1]), "r"(af[i][2]), "r"(af[i][3]),
                          "r"(bf[j][0]), "r"(bf[j][1]));
                }
        }
        s = (s == NSTG - 1) ? 0 : s + 1;
        sp = (sp == NSTG - 1) ? 0 : sp + 1;
    }

#pragma unroll
    for (int i = 0; i < 4; i++) {
        const int rr0 = bm + wm + i * 16 + g;
        const int rr1 = rr0 + 8;
#pragma unroll
        for (int j = 0; j < 4; j++) {
            const int cc = bn + wn + j * 8 + 2 * tig;
            float b0 = 0.f, b1 = 0.f;
            if (bias) { b0 = bias[cc]; b1 = bias[cc + 1]; }
            float2 v0, v1;
            v0.x = acc[i][j][0] + b0; v0.y = acc[i][j][1] + b1;
            v1.x = acc[i][j][2] + b0; v1.y = acc[i][j][3] + b1;
            if (MODE == 1) {
                v0.x = tf32r(v0.x); v0.y = tf32r(v0.y);
                v1.x = tf32r(v1.x); v1.y = tf32r(v1.y);
            }
            *(float2*)(Cb + (size_t)rr0 * ldc + cc) = v0;
            *(float2*)(Cb + (size_t)rr1 * ldc + cc) = v1;
        }
    }
}

// ---------------- gemm_core64: 128 threads, 4 warps of 64x64 ----------------
// (measured faster for the projection shapes; same accumulation order ->
//  bit-identical results). MODE: 1 = tf32-rounded store, 2 = TRANSPOSED store.
template<int MODE>
__device__ __forceinline__ void gemm_core64(
    const float* __restrict__ Ab, const float* __restrict__ Bb,
    const float* __restrict__ bias, float* __restrict__ Cb,
    int Kd, int lda, int ldb, int ldc, int bm, int bn) {
    extern __shared__ float smf[];
    uint32_t sbase = (uint32_t)__cvta_generic_to_shared(smf);
    sbase = (sbase + 1023u) & ~1023u;

    const int tid = threadIdx.x;
    const int lane = tid & 31;
    const int w = tid >> 5;             // 0..3
    const int wm = (w >> 1) * 64;
    const int wn = (w & 1) * 64;
    const int g = lane >> 2;
    const int tig = lane & 3;
    const int nk = Kd / BK;

    // loaders: 8 rows per thread per matrix (rows r0 + u*16)
    const int r0 = tid >> 3;            // 0..15
    const int ch = tid & 7;
    const uint32_t swoff = (uint32_t)((ch * 16) ^ ((r0 & 7) << 4));
    const uint32_t ldOffA = (uint32_t)(r0 * 128) + swoff;
    const float* gA0 = Ab + (size_t)(bm + r0) * lda + ch * 4;
    const float* gB0 = Bb + (size_t)(bn + r0) * ldb + ch * 4;
    const size_t gAs = 16 * (size_t)lda;
    const size_t gBs = 16 * (size_t)ldb;

    const int aRowOff = ((lane >> 3) & 1) * 8 + (lane & 7);
    const uint32_t aCS = (uint32_t)((lane >> 4) * 16);
    uint32_t aRB[4], aRX[4];
#pragma unroll
    for (int i = 0; i < 4; i++) {
        int row = wm + i * 16 + aRowOff;
        aRB[i] = (uint32_t)(row * 128);
        aRX[i] = (uint32_t)((row & 7) << 4);
    }
    const uint32_t bCS = (uint32_t)(((lane >> 3) & 1) * 16);
    uint32_t bRB[4], bRX[4];
#pragma unroll
    for (int p = 0; p < 4; p++) {
        int row = wn + p * 16 + ((lane >> 4) * 8) + (lane & 7);
        bRB[p] = (uint32_t)(row * 128);
        bRX[p] = (uint32_t)((row & 7) << 4);
    }

    float acc[4][8][4];
#pragma unroll
    for (int i = 0; i < 4; i++)
#pragma unroll
        for (int j = 0; j < 8; j++)
#pragma unroll
            for (int r = 0; r < 4; r++) acc[i][j][r] = 0.f;

#pragma unroll
    for (int t = 0; t < 2; t++) {
        const uint32_t ds = sbase + t * STG;
        const float* ga = gA0 + (size_t)t * BK;
        const float* gb = gB0 + (size_t)t * BK;
#pragma unroll
        for (int u = 0; u < 8; u++) {
            CPA16(ds + ldOffA + u * 2048, ga + u * gAs);
            CPA16(ds + TILE_B + ldOffA + u * 2048, gb + u * gBs);
        }
        asm volatile("cp.async.commit_group;");
    }

    int s = 0, sp = 2;
    for (int t = 0; t < nk; t++) {
        asm volatile("cp.async.wait_group 1;");
        __syncthreads();

        if (t + 2 < nk) {
            const uint32_t ds = sbase + sp * STG;
            const float* ga = gA0 + (size_t)(t + 2) * BK;
            const float* gb = gB0 + (size_t)(t + 2) * BK;
#pragma unroll
            for (int u = 0; u < 8; u++) {
                CPA16(ds + ldOffA + u * 2048, ga + u * gAs);
                CPA16(ds + TILE_B + ldOffA + u * 2048, gb + u * gBs);
            }
        }
        asm volatile("cp.async.commit_group;");

        const uint32_t aB = sbase + s * STG;
        const uint32_t bB = aB + TILE_B;
#pragma unroll
        for (int ks = 0; ks < 4; ks++) {
            const uint32_t kcol = (uint32_t)(ks * 32);
            uint32_t af[4][4], bf[8][2];
#pragma unroll
            for (int i = 0; i < 4; i++)
                LDSM4(af[i][0], af[i][1], af[i][2], af[i][3],
                      aB + aRB[i] + ((kcol + aCS) ^ aRX[i]));
#pragma unroll
            for (int p = 0; p < 4; p++)
                LDSM4(bf[2 * p][0], bf[2 * p][1], bf[2 * p + 1][0], bf[2 * p + 1][1],
                      bB + bRB[p] + ((kcol + bCS) ^ bRX[p]));
#pragma unroll
            for (int i = 0; i < 4; i++)
#pragma unroll
                for (int j = 0; j < 8; j++) {
                    asm volatile(
                        "mma.sync.aligned.m16n8k8.row.col.f32.tf32.tf32.f32 "
                        "{%0,%1,%2,%3}, {%4,%5,%6,%7}, {%8,%9}, {%0,%1,%2,%3};"
                        : "+f"(acc[i][j][0]), "+f"(acc[i][j][1]),
                          "+f"(acc[i][j][2]), "+f"(acc[i][j][3])
                        : "r"(af[i][0]), "r"(af[i][1]), "r"(af[i][2]), "r"(af[i][3]),
                          "r"(bf[j][0]), "r"(bf[j][1]));
                }
        }
        s = (s == NSTG - 1) ? 0 : s + 1;
        sp = (sp == NSTG - 1) ? 0 : sp + 1;
    }

    if (MODE == 2) {
        // transposed epilogue: SMEM [n][m] staging (pad 132)
        __syncthreads();
#pragma unroll
        for (int i = 0; i < 4; i++) {
            const int rr0 = wm + i * 16 + g;
            const int rr1 = rr0 + 8;
#pragma unroll
            for (int j = 0; j < 8; j++) {
                const int cc = wn + j * 8 + 2 * tig;
                const float b0 = bias[bn + cc];
                const float b1 = bias[bn + cc + 1];
                smf[(cc + 0) * 132 + rr0] = tf32r(acc[i][j][0] + b0);
                smf[(cc + 1) * 132 + rr0] = tf32r(acc[i][j][1] + b1);
                smf[(cc + 0) * 132 + rr1] = tf32r(acc[i][j][2] + b0);
                smf[(cc + 1) * 132 + rr1] = tf32r(acc[i][j][3] + b1);
            }
        }
        __syncthreads();
        // coalesced write: vT[(bn+tid)][bm .. bm+127]
        float* orow = Cb + (size_t)(bn + tid) * cM + bm;
        const float* srow = smf + tid * 132;
#pragma unroll
        for (int u = 0; u < 32; u++) {
            float4 vv;
            vv.x = srow[u * 4 + 0];
            vv.y = srow[u * 4 + 1];
            vv.z = srow[u * 4 + 2];
            vv.w = srow[u * 4 + 3];
            *(float4*)(orow + u * 4) = vv;
        }
    } else {
#pragma unroll
        for (int i = 0; i < 4; i++) {
            const int rr0 = bm + wm + i * 16 + g;
            const int rr1 = rr0 + 8;
#pragma unroll
            for (int j = 0; j < 8; j++) {
                const int cc = bn + wn + j * 8 + 2 * tig;
                float b0 = 0.f, b1 = 0.f;
                if (bias) { b0 = bias[cc]; b1 = bias[cc + 1]; }
                float2 v0, v1;
                v0.x = acc[i][j][0] + b0; v0.y = acc[i][j][1] + b1;
                v1.x = acc[i][j][2] + b0; v1.y = acc[i][j][3] + b1;
                if (MODE == 1) {
                    v0.x = tf32r(v0.x); v0.y = tf32r(v0.y);
                    v1.x = tf32r(v1.x); v1.y = tf32r(v1.y);
                }
                *(float2*)(Cb + (size_t)rr0 * ldc + cc) = v0;
                *(float2*)(Cb + (size_t)rr1 * ldc + cc) = v1;
            }
        }
    }
}

// fused q/k/v projections (128-thread core): grid (16, 64, 3)
__global__ __launch_bounds__(128, 2)
void gemm3_proj(const float* __restrict__ bq, const float* __restrict__ bk,
                const float* __restrict__ bv) {
    const int z = blockIdx.z;
    const int bm = blockIdx.y * 128, bn = blockIdx.x * 128;
    if (z == 0)
        gemm_core64<1>(g_qrot, g_wq, bq, g_q, cH, cH, cH, cH, bm, bn);
    else if (z == 1)
        gemm_core64<1>(g_krot, g_wk, bk, g_k, cH, cH, cH, cH, bm, bn);
    else
        gemm_core64<2>(g_vin, g_wv, bv, g_vT, cH, cH, cH, cM, bm, bn);
}

__global__ __launch_bounds__(256, 2)
void gemm_bat0(const float* __restrict__ A, const float* __restrict__ Bm,
               const float* __restrict__ bias, float* __restrict__ C,
               int Kd, int lda, int ldb, int ldc,
               size_t strA, size_t strB, size_t strC) {
    gemm_core<0>(A + blockIdx.z * strA, Bm + blockIdx.z * strB, bias,
                 C + blockIdx.z * strC, Kd, lda, ldb, ldc,
                 blockIdx.y * 128, blockIdx.x * 128);
}

__global__ __launch_bounds__(256, 2)
void gemm_bat1(const float* __restrict__ A, const float* __restrict__ Bm,
               const float* __restrict__ bias, float* __restrict__ C,
               int Kd, int lda, int ldb, int ldc,
               size_t strA, size_t strB, size_t strC) {
    gemm_core<1>(A + blockIdx.z * strA, Bm + blockIdx.z * strB, bias,
                 C + blockIdx.z * strC, Kd, lda, ldb, ldc,
                 blockIdx.y * 128, blockIdx.x * 128);
}

// ---------------- softmax (float4 vectorized; same reduction order) ---------
__global__ void softmax_kernel(float* __restrict__ Sc, float scale) {
    const size_t row = blockIdx.x;
    float4* p = (float4*)(Sc + row * (size_t)cS);   // 512 float4 per row
    const int tid = threadIdx.x;                    // 256 threads
    __shared__ float smax[8];
    __shared__ float ssum[8];

    float4 a = p[tid];
    float4 b = p[tid + 256];
    float v[8];
    v[0] = a.x * scale; v[1] = a.y * scale; v[2] = a.z * scale; v[3] = a.w * scale;
    v[4] = b.x * scale; v[5] = b.y * scale; v[6] = b.z * scale; v[7] = b.w * scale;

    float m = -CUDART_INF_F;
#pragma unroll
    for (int i = 0; i < 8; i++) m = fmaxf(m, v[i]);
#pragma unroll
    for (int o = 16; o > 0; o >>= 1)
        m = fmaxf(m, __shfl_xor_sync(0xffffffffu, m, o));
    if ((tid & 31) == 0) smax[tid >> 5] = m;
    __syncthreads();
    m = smax[0];
#pragma unroll
    for (int w = 1; w < 8; w++) m = fmaxf(m, smax[w]);

    float s = 0.f;
#pragma unroll
    for (int i = 0; i < 8; i++) {
        v[i] = expf(v[i] - m);
        s += v[i];
    }
#pragma unroll
    for (int o = 16; o > 0; o >>= 1)
        s += __shfl_xor_sync(0xffffffffu, s, o);
    if ((tid & 31) == 0) ssum[tid >> 5] = s;
    __syncthreads();
    s = 0.f;
#pragma unroll
    for (int w = 0; w < 8; w++) s += ssum[w];
    const float inv = 1.0f / s;

    a.x = tf32r(v[0] * inv); a.y = tf32r(v[1] * inv);
    a.z = tf32r(v[2] * inv); a.w = tf32r(v[3] * inv);
    b.x = tf32r(v[4] * inv); b.y = tf32r(v[5] * inv);
    b.z = tf32r(v[6] * inv); b.w = tf32r(v[7] * inv);
    p[tid] = a;
    p[tid + 256] = b;
}

// ---------------- launch ----------------------------------------------------
extern "C" void kernel_launch(void* const* d_in, const int* in_sizes, int n_in,
                              void* d_out, int out_size) {
    const float* query = (const float*)d_in[0];
    const float* key_  = (const float*)d_in[1];
    const float* value = (const float*)d_in[2];
    const float* Wq = (const float*)d_in[3];
    const float* bq = (const float*)d_in[4];
    const float* Wk = (const float*)d_in[5];
    const float* bk = (const float*)d_in[6];
    const float* Wv = (const float*)d_in[7];
    const float* bv = (const float*)d_in[8];
    const float* Wo = (const float*)d_in[9];
    const float* bo = (const float*)d_in[10];
    float* out = (float*)d_out;

    float *p_vT, *p_s, *p_ctx, *p_q, *p_k, *p_wo;
    cudaGetSymbolAddress((void**)&p_vT, g_vT);
    cudaGetSymbolAddress((void**)&p_s, g_s);
    cudaGetSymbolAddress((void**)&p_ctx, g_ctx);
    cudaGetSymbolAddress((void**)&p_q, g_q);
    cudaGetSymbolAddress((void**)&p_k, g_k);
    cudaGetSymbolAddress((void**)&p_wo, g_wo);

    cudaFuncSetAttribute(gemm3_proj,
                         cudaFuncAttributeMaxDynamicSharedMemorySize, GEMM_SMEM);
    cudaFuncSetAttribute(gemm_bat0,
                         cudaFuncAttributeMaxDynamicSharedMemorySize, GEMM_SMEM);
    cudaFuncSetAttribute(gemm_bat1,
                         cudaFuncAttributeMaxDynamicSharedMemorySize, GEMM_SMEM);

    // 1) RoPE tables; RoPE(q,k) + round(v) pair-processed
    rope_tables_kernel<<<(cS * cH2 + 255) / 256, 256>>>();
    rope_apply_v_kernel<<<(int)((size_t)cM * (cH2 / 4) / 256), 256>>>(query, key_, value);

    // 2) round all weights (one launch)
    round_weights_kernel<<<dim3((unsigned)(WN / 4 / 256), 4), 256>>>(Wq, Wk, Wv, Wo);

    // 3) fused q/k/v projections (128-thread 64x64 core); v written transposed
    gemm3_proj<<<dim3(16, 64, 3), 128, GEMM_SMEM>>>(bq, bk, bv);

    // 4) scores = q @ k^T (batched over B)
    gemm_bat0<<<dim3(16, 16, cB), 256, GEMM_SMEM>>>(p_q, p_k, nullptr, p_s,
                                                    cH, cH, cH, cS, SH, SH, SSz);

    // 5) softmax
    const float scale = 1.0f / sqrtf((float)cH);
    softmax_kernel<<<cB * cS, 256>>>(p_s, scale);

    // 6) context = probs @ vT^T (batched)
    gemm_bat1<<<dim3(16, 16, cB), 256, GEMM_SMEM>>>(p_s, p_vT, nullptr, p_ctx,
                                                    cS, cS, cM, cH, SSz, (size_t)cS, SH);

    // 7) out = ctx @ Wo^T + bo
    gemm_bat0<<<dim3(16, 64, 1), 256, GEMM_SMEM>>>(p_ctx, p_wo, bo, out,
                                                   cH, cH, cH, cH, 0, 0, 0);
}